// round 5
// baseline (speedup 1.0000x reference)
#include <cuda_runtime.h>
#include <cstdint>

#define NPIX 9216            // H*W = 96*96
#define BATCH 2
#define TOT (BATCH*NPIX)     // 18432
#define RPB 8                // attention rows per block
#define LOG2E 1.4426950408889634f

__device__ __forceinline__ float ex2(float x) {
    float r;
    asm("ex2.approx.ftz.f32 %0, %1;" : "=f"(r) : "f"(x));
    return r;
}
__device__ __forceinline__ float rcp(float x) {
    float r;
    asm("rcp.approx.ftz.f32 %0, %1;" : "=f"(r) : "f"(x));
    return r;
}

// Single fused kernel: channel-softmax + attention + softmax + out + conv1x1 epilogue.
// Per block: RPB attention rows; p tile computed from x into smem once.
//   p_m = sigmoid(x0-x1); e_m = 2^(a_r * p_m), a_r = (2 p_r - 1) log2e
//   attn[row,m] = e_m / S_r ; y[row] = sigmoid(conv(gamma*out + xs))
__global__ void __launch_bounds__(256, 3)
k_fused(const float* __restrict__ x,
        const float* __restrict__ w, const float* __restrict__ cb,
        const float* __restrict__ gm,
        float* __restrict__ y, float* __restrict__ attn) {
    const int tid = threadIdx.x;
    const int lane = tid & 31, wid = tid >> 5;
    const int rowBase = blockIdx.x * RPB;      // 9216 % RPB == 0: no batch straddle
    const int b = rowBase / NPIX;

    __shared__ __align__(16) float sp[NPIX];   // 36 KB p tile
    __shared__ float sS[8], sT[8];

    // Build p tile from x (x is 144 KB total, L2-resident)
    {
        const float4* __restrict__ x0 = reinterpret_cast<const float4*>(x + (size_t)(b*2+0)*NPIX);
        const float4* __restrict__ x1 = reinterpret_cast<const float4*>(x + (size_t)(b*2+1)*NPIX);
        float4* dst = reinterpret_cast<float4*>(sp);
#pragma unroll
        for (int k = 0; k < 9; k++) {
            float4 a = x0[tid + k*256];
            float4 c = x1[tid + k*256];
            float4 p;
            p.x = rcp(1.0f + ex2((c.x - a.x) * LOG2E));
            p.y = rcp(1.0f + ex2((c.y - a.y) * LOG2E));
            p.z = rcp(1.0f + ex2((c.z - a.z) * LOG2E));
            p.w = rcp(1.0f + ex2((c.w - a.w) * LOG2E));
            dst[tid + k*256] = p;
        }
    }
    __syncthreads();

    const float4* sp4 = reinterpret_cast<const float4*>(sp);

#pragma unroll 1
    for (int r = 0; r < RPB; r++) {
        const int row = rowBase + r;
        const float a2 = (2.0f * sp[row - b*NPIX] - 1.0f) * LOG2E;

        float E[36];                   // full per-thread e cache (store phase = FMUL+STG only)
        float S = 0.0f, T = 0.0f;
#pragma unroll
        for (int k = 0; k < 9; k++) {
            float4 pv = sp4[tid + k*256];
            float e0 = ex2(a2 * pv.x);
            float e1 = ex2(a2 * pv.y);
            float e2 = ex2(a2 * pv.z);
            float e3 = ex2(a2 * pv.w);
            E[4*k+0]=e0; E[4*k+1]=e1; E[4*k+2]=e2; E[4*k+3]=e3;
            S += (e0 + e1) + (e2 + e3);
            T = fmaf(pv.x, e0, T); T = fmaf(pv.y, e1, T);
            T = fmaf(pv.z, e2, T); T = fmaf(pv.w, e3, T);
        }

        // block reduce S, T
#pragma unroll
        for (int o = 16; o > 0; o >>= 1) {
            S += __shfl_xor_sync(0xFFFFFFFFu, S, o);
            T += __shfl_xor_sync(0xFFFFFFFFu, T, o);
        }
        __syncthreads();               // protect sS/sT reuse across rows
        if (lane == 0) { sS[wid] = S; sT[wid] = T; }
        __syncthreads();
        float St = ((sS[0]+sS[1]) + (sS[2]+sS[3])) + ((sS[4]+sS[5]) + (sS[6]+sS[7]));
        float invS = 1.0f / St;

        if (tid == 0) {                // fused conv1x1 + sigmoid epilogue
            float Tt = ((sT[0]+sT[1]) + (sT[2]+sT[3])) + ((sT[4]+sT[5]) + (sT[6]+sT[7]));
            float o0 = Tt * invS;
            float p  = sp[row - b*NPIX];
            float g  = gm[0];
            float pre0 = fmaf(g, o0, p);
            float pre1 = fmaf(g, 1.0f - o0, 1.0f - p);
            float t = fmaf(w[0], pre0, fmaf(w[1], pre1, cb[0]));
            y[row] = 1.0f / (1.0f + __expf(-t));
        }

        float4* __restrict__ out4 =
            reinterpret_cast<float4*>(attn + (size_t)row * NPIX);
#pragma unroll
        for (int k = 0; k < 9; k++) {
            float4 o;
            o.x = E[4*k+0] * invS;
            o.y = E[4*k+1] * invS;
            o.z = E[4*k+2] * invS;
            o.w = E[4*k+3] * invS;
            out4[tid + k*256] = o;     // coalesced 128B streaming stores
        }
    }
}

extern "C" void kernel_launch(void* const* d_in, const int* in_sizes, int n_in,
                              void* d_out, int out_size) {
    const float* x  = (const float*)d_in[0];   // [2,2,96,96]
    const float* w  = (const float*)d_in[1];   // [2]
    const float* cb = (const float*)d_in[2];   // [1]
    const float* gm = (const float*)d_in[3];   // [1]
    float* out = (float*)d_out;                // [18432 y | 2*9216*9216 attn]

    k_fused<<<TOT / RPB, 256>>>(x, w, cb, gm, out, out + TOT);
}

// round 6
// speedup vs baseline: 1.0376x; 1.0376x over previous
#include <cuda_runtime.h>
#include <cstdint>

#define NPIX 9216            // H*W = 96*96
#define BATCH 2
#define TOT (BATCH*NPIX)     // 18432
#define RPB 4                // attention rows per block (small quantum -> short drain tail)

__device__ float g_p[TOT];   // p = sigmoid(x0-x1)   (channel-0 softmax)
__device__ float g_a[TOT];   // a = (2p-1)*log2(e)   (premultiplied row scale)

__device__ __forceinline__ float ex2(float x) {
    float r;
    asm("ex2.approx.ftz.f32 %0, %1;" : "=f"(r) : "f"(x));
    return r;
}

// Kernel 1: per-pixel prep (done ONCE -- cheap, fully overlapped in graph replay)
__global__ void k_prep(const float* __restrict__ x) {
    int i = blockIdx.x * blockDim.x + threadIdx.x;
    if (i >= TOT) return;
    int b = i / NPIX;
    int n = i - b * NPIX;
    float x0 = x[(size_t)(b * 2 + 0) * NPIX + n];
    float x1 = x[(size_t)(b * 2 + 1) * NPIX + n];
    float p = 1.0f / (1.0f + __expf(x1 - x0));
    g_p[i] = p;
    g_a[i] = (2.0f * p - 1.0f) * 1.4426950408889634f;  // log2(e)
}

// Kernel 2: RPB attention rows per block; p tile cached in smem.
//   e_m = 2^(a_r * p_m) ; attn[row,m] = e_m / S ; y[row] fused conv1x1+sigmoid
__global__ void __launch_bounds__(256, 3)
k_attn(const float* __restrict__ w, const float* __restrict__ cb,
       const float* __restrict__ gm,
       float* __restrict__ y, float* __restrict__ attn) {
    const int tid = threadIdx.x;
    const int lane = tid & 31, wid = tid >> 5;
    const int rowBase = blockIdx.x * RPB;      // 9216 % RPB == 0: no batch straddle
    const int b = rowBase / NPIX;

    __shared__ __align__(16) float sp[NPIX];   // 36 KB p tile
    __shared__ float sS[8], sT[8];

    {   // load p tile once per block (L2-resident source)
        const float4* __restrict__ src = reinterpret_cast<const float4*>(g_p + b * NPIX);
        float4* dst = reinterpret_cast<float4*>(sp);
#pragma unroll
        for (int k = 0; k < 9; k++)
            dst[tid + k * 256] = src[tid + k * 256];
    }
    __syncthreads();

    const float4* sp4 = reinterpret_cast<const float4*>(sp);

#pragma unroll 1
    for (int r = 0; r < RPB; r++) {
        const int row = rowBase + r;
        const float a2 = g_a[row];             // L2 hit

        float E[36];                   // full per-thread e cache (store phase = FMUL+STG only)
        float S = 0.0f, T = 0.0f;
#pragma unroll
        for (int k = 0; k < 9; k++) {
            float4 pv = sp4[tid + k * 256];
            float e0 = ex2(a2 * pv.x);
            float e1 = ex2(a2 * pv.y);
            float e2 = ex2(a2 * pv.z);
            float e3 = ex2(a2 * pv.w);
            E[4*k+0]=e0; E[4*k+1]=e1; E[4*k+2]=e2; E[4*k+3]=e3;
            S += (e0 + e1) + (e2 + e3);
            T = fmaf(pv.x, e0, T); T = fmaf(pv.y, e1, T);
            T = fmaf(pv.z, e2, T); T = fmaf(pv.w, e3, T);
        }

        // block reduce S, T
#pragma unroll
        for (int o = 16; o > 0; o >>= 1) {
            S += __shfl_xor_sync(0xFFFFFFFFu, S, o);
            T += __shfl_xor_sync(0xFFFFFFFFu, T, o);
        }
        __syncthreads();               // protect sS/sT reuse across rows
        if (lane == 0) { sS[wid] = S; sT[wid] = T; }
        __syncthreads();
        float St = ((sS[0]+sS[1]) + (sS[2]+sS[3])) + ((sS[4]+sS[5]) + (sS[6]+sS[7]));
        float invS = 1.0f / St;

        if (tid == 0) {                // fused conv1x1 + sigmoid epilogue
            float Tt = ((sT[0]+sT[1]) + (sT[2]+sT[3])) + ((sT[4]+sT[5]) + (sT[6]+sT[7]));
            float o0 = Tt * invS;
            float p  = sp[row - b * NPIX];
            float g  = gm[0];
            float pre0 = fmaf(g, o0, p);
            float pre1 = fmaf(g, 1.0f - o0, 1.0f - p);
            float t = fmaf(w[0], pre0, fmaf(w[1], pre1, cb[0]));
            y[row] = 1.0f / (1.0f + __expf(-t));
        }

        float4* __restrict__ out4 =
            reinterpret_cast<float4*>(attn + (size_t)row * NPIX);
#pragma unroll
        for (int k = 0; k < 9; k++) {
            float4 o;
            o.x = E[4*k+0] * invS;
            o.y = E[4*k+1] * invS;
            o.z = E[4*k+2] * invS;
            o.w = E[4*k+3] * invS;
            out4[tid + k * 256] = o;   // coalesced 128B streaming stores
        }
    }
}

extern "C" void kernel_launch(void* const* d_in, const int* in_sizes, int n_in,
                              void* d_out, int out_size) {
    const float* x  = (const float*)d_in[0];   // [2,2,96,96]
    const float* w  = (const float*)d_in[1];   // [2]
    const float* cb = (const float*)d_in[2];   // [1]
    const float* gm = (const float*)d_in[3];   // [1]
    float* out = (float*)d_out;                // [18432 y | 2*9216*9216 attn]

    k_prep<<<(TOT + 127) / 128, 128>>>(x);
    k_attn<<<TOT / RPB, 256>>>(w, cb, gm, out, out + TOT);
}